// round 2
// baseline (speedup 1.0000x reference)
#include <cuda_runtime.h>
#include <cuda_bf16.h>
#include <cstdint>

#define B_N 1024
#define D_N 512
#define C_N 100000
#define MARGIN 0.1f
#define EPSV 1e-8f

#define NT 128                       // classes per CTA tile
#define NTILES ((C_N + NT - 1) / NT) // 782
#define MB 128                       // rows per m-block
#define KC 64                        // k chunk (bf16 cols staged for X)
#define ES_STR 520                   // E smem row stride (halves)
#define XS_STR 72                    // X smem row stride (halves)

#define SMEM_BYTES ((NT * ES_STR + MB * XS_STR) * 2 + (NT + MB + MB) * 4)

__device__ __align__(128) __nv_bfloat16 g_Xn[B_N * D_N];
__device__ float g_t[B_N];
__device__ float g_partial[NTILES * B_N];

// ---------------------------------------------------------------------------
// Kernel 1: row-normalize inputs, store bf16
// ---------------------------------------------------------------------------
__global__ void k_norm(const float* __restrict__ X) {
    int b = blockIdx.x;
    int tid = threadIdx.x; // 128 threads
    const float* x = X + (size_t)b * D_N;
    float v[4];
    float ss = 0.f;
#pragma unroll
    for (int j = 0; j < 4; j++) {
        v[j] = x[tid + j * 128];
        ss += v[j] * v[j];
    }
    __shared__ float sm[128];
    sm[tid] = ss;
    __syncthreads();
    for (int s = 64; s > 0; s >>= 1) {
        if (tid < s) sm[tid] += sm[tid + s];
        __syncthreads();
    }
    float inv = 1.0f / fmaxf(sqrtf(sm[0]), EPSV);
#pragma unroll
    for (int j = 0; j < 4; j++)
        g_Xn[(size_t)b * D_N + tid + j * 128] = __float2bfloat16(v[j] * inv);
}

// ---------------------------------------------------------------------------
// Kernel 2: fp32-exact target cosine per sample (targets are int32!)
// ---------------------------------------------------------------------------
__global__ void k_target(const float* __restrict__ X, const float* __restrict__ E,
                         const int* __restrict__ T) {
    int b = blockIdx.x;
    int tid = threadIdx.x; // 128 threads
    int tg = T[b];
    tg = max(0, min(tg, C_N - 1)); // defensive clamp
    const float* x = X + (size_t)b * D_N;
    const float* e = E + (size_t)tg * D_N;
    float sxx = 0.f, see = 0.f, sxe = 0.f;
#pragma unroll
    for (int j = 0; j < 4; j++) {
        float xv = x[tid + j * 128];
        float ev = e[tid + j * 128];
        sxx += xv * xv;
        see += ev * ev;
        sxe += xv * ev;
    }
    __shared__ float s1[128], s2[128], s3[128];
    s1[tid] = sxx; s2[tid] = see; s3[tid] = sxe;
    __syncthreads();
    for (int s = 64; s > 0; s >>= 1) {
        if (tid < s) { s1[tid] += s1[tid + s]; s2[tid] += s2[tid + s]; s3[tid] += s3[tid + s]; }
        __syncthreads();
    }
    if (tid == 0)
        g_t[b] = s3[0] / (fmaxf(sqrtf(s1[0]), EPSV) * fmaxf(sqrtf(s2[0]), EPSV));
}

// ---------------------------------------------------------------------------
// Kernel 3: fused GEMM (bf16 mma.sync) + inv-norm scale + hinge + row reduce
// One CTA per 128-class tile; E slice loaded ONCE into smem as bf16.
// ---------------------------------------------------------------------------
__global__ __launch_bounds__(256, 1) void k_main(const float* __restrict__ E) {
    extern __shared__ __align__(16) char smem[];
    __nv_bfloat16* Es = (__nv_bfloat16*)smem;            // [NT][ES_STR]
    __nv_bfloat16* Xs = Es + NT * ES_STR;                // [MB][XS_STR]
    float* invn = (float*)(Xs + MB * XS_STR);            // [NT]
    float* ts = invn + NT;                               // [MB]
    float* redbuf = ts + MB;                             // [MB]

    int tid = threadIdx.x;
    int lane = tid & 31, wid = tid >> 5;
    int warp_m = wid >> 2;  // 0..1 -> 64 rows
    int warp_n = wid & 3;   // 0..3 -> 32 cols
    int c0 = blockIdx.x * NT;

    // ---- Phase 1: load E tile (fp32 -> bf16), compute inv-norms ----
    {
        int cl = tid >> 1;        // class within tile
        int pr = tid & 1;         // pair index
        long long gc = (long long)c0 + cl;
        bool vld = (gc < C_N);
        const float4* src = (const float4*)(E + gc * (long long)D_N);
        float ss = 0.f;
#pragma unroll 8
        for (int i = 0; i < 64; i++) {
            int f4 = pr + 2 * i;
            float4 v = vld ? src[f4] : make_float4(0.f, 0.f, 0.f, 0.f);
            ss += v.x * v.x + v.y * v.y + v.z * v.z + v.w * v.w;
            __nv_bfloat162* dst = (__nv_bfloat162*)&Es[cl * ES_STR + f4 * 4];
            dst[0] = __floats2bfloat162_rn(v.x, v.y);
            dst[1] = __floats2bfloat162_rn(v.z, v.w);
        }
        ss += __shfl_xor_sync(0xffffffffu, ss, 1);
        if (pr == 0) invn[cl] = vld ? (1.0f / fmaxf(sqrtf(ss), EPSV)) : 0.f;
    }
    __syncthreads();

    // ---- Phase 2: loop over row blocks ----
    for (int mb = 0; mb < B_N / MB; mb++) {
        int m0 = mb * MB;
        __syncthreads(); // protect redbuf reads of previous iteration
        if (tid < MB) {
            ts[tid] = g_t[m0 + tid];
            redbuf[tid] = 0.f;
        }
        float acc[4][4][4];
#pragma unroll
        for (int im = 0; im < 4; im++)
#pragma unroll
            for (int in = 0; in < 4; in++)
#pragma unroll
                for (int r = 0; r < 4; r++) acc[im][in][r] = 0.f;

        for (int kc = 0; kc < D_N / KC; kc++) {
            __syncthreads();
            // stage X chunk [MB x KC] bf16 from global (L2-hot)
#pragma unroll
            for (int j = 0; j < 4; j++) {
                int seg = tid + j * 256;
                int row = seg >> 3, c8 = seg & 7;
                const uint4* s =
                    (const uint4*)&g_Xn[(size_t)(m0 + row) * D_N + kc * KC + c8 * 8];
                *(uint4*)&Xs[row * XS_STR + c8 * 8] = *s;
            }
            __syncthreads();

#pragma unroll
            for (int ks = 0; ks < 4; ks++) {
                uint32_t a[4][4], bb[4][2];
                int arow = lane >> 2;
                int acq = (lane & 3) * 2 + ks * 16;
#pragma unroll
                for (int im = 0; im < 4; im++) {
                    const __nv_bfloat16* p =
                        &Xs[(warp_m * 64 + im * 16 + arow) * XS_STR + acq];
                    a[im][0] = *(const uint32_t*)p;
                    a[im][1] = *(const uint32_t*)(p + 8 * XS_STR);
                    a[im][2] = *(const uint32_t*)(p + 8);
                    a[im][3] = *(const uint32_t*)(p + 8 * XS_STR + 8);
                }
                int bk = kc * KC + ks * 16 + (lane & 3) * 2;
#pragma unroll
                for (int in = 0; in < 4; in++) {
                    const __nv_bfloat16* q =
                        &Es[(warp_n * 32 + in * 8 + (lane >> 2)) * ES_STR + bk];
                    bb[in][0] = *(const uint32_t*)q;
                    bb[in][1] = *(const uint32_t*)(q + 8);
                }
#pragma unroll
                for (int im = 0; im < 4; im++)
#pragma unroll
                    for (int in = 0; in < 4; in++)
                        asm volatile(
                            "mma.sync.aligned.m16n8k16.row.col.f32.bf16.bf16.f32 "
                            "{%0,%1,%2,%3}, {%4,%5,%6,%7}, {%8,%9}, {%0,%1,%2,%3};"
                            : "+f"(acc[im][in][0]), "+f"(acc[im][in][1]),
                              "+f"(acc[im][in][2]), "+f"(acc[im][in][3])
                            : "r"(a[im][0]), "r"(a[im][1]), "r"(a[im][2]),
                              "r"(a[im][3]), "r"(bb[in][0]), "r"(bb[in][1]));
            }
        }

        // ---- epilogue: scale by inv-norm, hinge, per-row reduce ----
        float rsum[8];
#pragma unroll
        for (int j = 0; j < 8; j++) rsum[j] = 0.f;
#pragma unroll
        for (int in = 0; in < 4; in++) {
            int cL = warp_n * 32 + in * 8 + (lane & 3) * 2;
            float i0 = invn[cL], i1 = invn[cL + 1];
            float v0 = (c0 + cL < C_N) ? 1.f : 0.f;
            float v1 = (c0 + cL + 1 < C_N) ? 1.f : 0.f;
#pragma unroll
            for (int im = 0; im < 4; im++) {
                int r0 = warp_m * 64 + im * 16 + (lane >> 2);
                float t0 = ts[r0], t1 = ts[r0 + 8];
                rsum[im * 2] += v0 * fmaxf(0.f, MARGIN - t0 + acc[im][in][0] * i0);
                rsum[im * 2] += v1 * fmaxf(0.f, MARGIN - t0 + acc[im][in][1] * i1);
                rsum[im * 2 + 1] += v0 * fmaxf(0.f, MARGIN - t1 + acc[im][in][2] * i0);
                rsum[im * 2 + 1] += v1 * fmaxf(0.f, MARGIN - t1 + acc[im][in][3] * i1);
            }
        }
#pragma unroll
        for (int j = 0; j < 8; j++) {
            rsum[j] += __shfl_xor_sync(0xffffffffu, rsum[j], 1);
            rsum[j] += __shfl_xor_sync(0xffffffffu, rsum[j], 2);
        }
        if ((lane & 3) == 0) {
#pragma unroll
            for (int im = 0; im < 4; im++) {
                int r = warp_m * 64 + im * 16 + (lane >> 2);
                atomicAdd(&redbuf[r], rsum[im * 2]);
                atomicAdd(&redbuf[r + 8], rsum[im * 2 + 1]);
            }
        }
        __syncthreads();
        if (tid < MB)
            g_partial[(size_t)blockIdx.x * B_N + m0 + tid] = redbuf[tid];
    }
}

// ---------------------------------------------------------------------------
// Kernel 4: final reduction to scalar
// ---------------------------------------------------------------------------
__global__ void k_final(float* __restrict__ out) {
    int tid = threadIdx.x; // 1024 threads
    float s = 0.f;
    for (int t = 0; t < NTILES; t++) s += g_partial[(size_t)t * B_N + tid];
#pragma unroll
    for (int off = 16; off > 0; off >>= 1) s += __shfl_xor_sync(0xffffffffu, s, off);
    __shared__ float sm[32];
    int lane = tid & 31, wid = tid >> 5;
    if (lane == 0) sm[wid] = s;
    __syncthreads();
    if (tid < 32) {
        float v = sm[tid];
#pragma unroll
        for (int off = 16; off > 0; off >>= 1) v += __shfl_xor_sync(0xffffffffu, v, off);
        if (tid == 0) out[0] = v / (float)B_N - MARGIN;
    }
}

// ---------------------------------------------------------------------------
extern "C" void kernel_launch(void* const* d_in, const int* in_sizes, int n_in,
                              void* d_out, int out_size) {
    const float* X = (const float*)d_in[0];   // [1024, 512] fp32
    const float* E = (const float*)d_in[1];   // [100000, 512] fp32
    const int* T = (const int*)d_in[2];       // [1024] int32 (JAX x64 disabled)
    float* out = (float*)d_out;

    cudaFuncSetAttribute(k_main, cudaFuncAttributeMaxDynamicSharedMemorySize,
                         SMEM_BYTES);

    k_norm<<<B_N, 128>>>(X);
    k_target<<<B_N, 128>>>(X, E, T);
    k_main<<<NTILES, 256, SMEM_BYTES>>>(E);
    k_final<<<1, 1024>>>(out);
}

// round 4
// speedup vs baseline: 1.2860x; 1.2860x over previous
#include <cuda_runtime.h>
#include <cuda_bf16.h>
#include <cstdint>

#define B_N 1024
#define D_N 512
#define C_N 100000
#define MARGIN 0.1f
#define EPSV 1e-8f

#define NT 128                       // classes per CTA tile
#define NTILES 782                   // ceil(100000/128)
#define NMB 8                        // 1024/128 row blocks
#define NKC 8                        // 512/64 k-chunks per m-block
#define NSTEP (NMB * NKC)            // 64 chunks total
#define ES_STR 520                   // E smem row stride in halves (1040B, 16B-mult)
#define XR_BYTES 144                 // X chunk row stride bytes (72 halves)

#define ES_BYTES (NT * ES_STR * 2)   // 133120
#define XC_OFF ES_BYTES
#define XC_BYTES (128 * XR_BYTES)    // 18432
#define NBUF 3
#define INVN_OFF (XC_OFF + NBUF * XC_BYTES)   // 188416
#define VM_OFF (INVN_OFF + 512)
#define SMEM_BYTES (VM_OFF + 512)             // 189440

__device__ __align__(128) __nv_bfloat16 g_Xn[B_N * D_N];
__device__ float g_t[B_N];
__device__ float g_partial[NTILES];

// ---------------------------------------------------------------------------
__device__ __forceinline__ uint32_t smem_u32(const void* p) {
    uint32_t a;
    asm("{ .reg .u64 t; cvta.to.shared.u64 t, %1; cvt.u32.u64 %0, t; }" : "=r"(a) : "l"(p));
    return a;
}
__device__ __forceinline__ void cp16(uint32_t dst, const void* src) {
    asm volatile("cp.async.cg.shared.global [%0], [%1], 16;" :: "r"(dst), "l"(src));
}
__device__ __forceinline__ void cp_commit() {
    asm volatile("cp.async.commit_group;" ::: "memory");
}
__device__ __forceinline__ void ldsm4(uint32_t* r, uint32_t a) {
    asm volatile("ldmatrix.sync.aligned.m8n8.x4.shared.b16 {%0,%1,%2,%3}, [%4];"
                 : "=r"(r[0]), "=r"(r[1]), "=r"(r[2]), "=r"(r[3]) : "r"(a));
}

// ---------------------------------------------------------------------------
// Kernel 1: row-normalize inputs, store bf16 (linear layout)
// ---------------------------------------------------------------------------
__global__ void k_norm(const float* __restrict__ X) {
    int b = blockIdx.x;
    int t = threadIdx.x; // 128 threads, 4 floats each
    float4 v = *(const float4*)(X + (size_t)b * D_N + 4 * t);
    float ss = v.x * v.x + v.y * v.y + v.z * v.z + v.w * v.w;
    __shared__ float sm[128];
    sm[t] = ss;
    __syncthreads();
    for (int s = 64; s > 0; s >>= 1) {
        if (t < s) sm[t] += sm[t + s];
        __syncthreads();
    }
    float inv = 1.0f / fmaxf(sqrtf(sm[0]), EPSV);
    __nv_bfloat162 h0 = __floats2bfloat162_rn(v.x * inv, v.y * inv);
    __nv_bfloat162 h1 = __floats2bfloat162_rn(v.z * inv, v.w * inv);
    uint2 pk;
    pk.x = *(uint32_t*)&h0;
    pk.y = *(uint32_t*)&h1;
    *(uint2*)(g_Xn + (size_t)b * D_N + 4 * t) = pk;
}

// ---------------------------------------------------------------------------
// Kernel 2: fp32-exact target cosine (targets int32)
// ---------------------------------------------------------------------------
__global__ void k_target(const float* __restrict__ X, const float* __restrict__ E,
                         const int* __restrict__ T) {
    int b = blockIdx.x;
    int tid = threadIdx.x;
    int tg = max(0, min(T[b], C_N - 1));
    const float* x = X + (size_t)b * D_N;
    const float* e = E + (size_t)tg * D_N;
    float sxx = 0.f, see = 0.f, sxe = 0.f;
#pragma unroll
    for (int j = 0; j < 4; j++) {
        float xv = x[tid + j * 128];
        float ev = e[tid + j * 128];
        sxx += xv * xv; see += ev * ev; sxe += xv * ev;
    }
    __shared__ float s1[128], s2[128], s3[128];
    s1[tid] = sxx; s2[tid] = see; s3[tid] = sxe;
    __syncthreads();
    for (int s = 64; s > 0; s >>= 1) {
        if (tid < s) { s1[tid] += s1[tid + s]; s2[tid] += s2[tid + s]; s3[tid] += s3[tid + s]; }
        __syncthreads();
    }
    if (tid == 0)
        g_t[b] = s3[0] / (fmaxf(sqrtf(s1[0]), EPSV) * fmaxf(sqrtf(s2[0]), EPSV));
}

// ---------------------------------------------------------------------------
// Kernel 3: bf16 mma.sync GEMM, ldmatrix feeds, cp.async 3-buffer pipeline,
// fused hinge epilogue -> one scalar per CTA.
// ---------------------------------------------------------------------------
__global__ __launch_bounds__(256, 1) void k_main(const float* __restrict__ E) {
    extern __shared__ __align__(1024) unsigned char smem[];
    uint32_t sbase = smem_u32(smem);
    float* invn = (float*)(smem + INVN_OFF);
    float* vmsk = (float*)(smem + VM_OFF);
    int tid = threadIdx.x, lane = tid & 31, wid = tid >> 5;
    int warp_m = wid >> 2;  // 0..1 -> 64 rows
    int warp_n = wid & 3;   // 0..3 -> 32 cols
    int c0 = blockIdx.x * NT;

    // ---- Phase 1: E tile fp32->bf16 + inv-norms + validity mask ----
    {
        int cl = tid >> 1, pr = tid & 1;
        int gc = c0 + cl;
        bool vld = gc < C_N;
        const float4* src = (const float4*)(E + (size_t)(vld ? gc : 0) * D_N);
        __nv_bfloat16* Es = (__nv_bfloat16*)smem;
        float ss = 0.f;
#pragma unroll 8
        for (int i = 0; i < 64; i++) {
            int f4 = pr + 2 * i;
            float4 v = vld ? src[f4] : make_float4(0.f, 0.f, 0.f, 0.f);
            ss += v.x * v.x + v.y * v.y + v.z * v.z + v.w * v.w;
            __nv_bfloat162 h0 = __floats2bfloat162_rn(v.x, v.y);
            __nv_bfloat162 h1 = __floats2bfloat162_rn(v.z, v.w);
            uint2 pk;
            pk.x = *(uint32_t*)&h0;
            pk.y = *(uint32_t*)&h1;
            *(uint2*)&Es[cl * ES_STR + f4 * 4] = pk;
        }
        ss += __shfl_xor_sync(0xffffffffu, ss, 1);
        if (pr == 0) {
            invn[cl] = vld ? (1.0f / fmaxf(sqrtf(ss), EPSV)) : 0.f;
            vmsk[cl] = vld ? 1.f : 0.f;
        }
    }
    __syncthreads();

    // ---- fragment address precompute (buffer/chunk-relative, bytes) ----
    uint32_t aRow[4];
#pragma unroll
    for (int im = 0; im < 4; im++)
        aRow[im] = (uint32_t)((warp_m * 64 + im * 16 + (lane & 15)) * XR_BYTES +
                              ((lane >> 4) & 1) * 16);
    uint32_t bRow[2];
#pragma unroll
    for (int g = 0; g < 2; g++)
        bRow[g] = (uint32_t)((warp_n * 32 + g * 16 + (lane & 7) +
                              ((lane >> 4) & 1) * 8) * (ES_STR * 2) +
                             ((lane >> 3) & 1) * 16);

    // ---- staging helper (lambda-free, macro-ish) ----
    auto stage = [&](int s, int buf) {
        int mb = s >> 3, kc = s & 7;
        const char* src = (const char*)g_Xn + (size_t)mb * 128 * 1024 + kc * 128;
        uint32_t dst = sbase + XC_OFF + buf * XC_BYTES;
#pragma unroll
        for (int j = 0; j < 4; j++) {
            int i = tid + j * 256;
            int row = i >> 3, seg = i & 7;
            cp16(dst + row * XR_BYTES + seg * 16, src + (size_t)row * 1024 + seg * 16);
        }
        cp_commit();
    };

    float acc[4][4][4];
#pragma unroll
    for (int im = 0; im < 4; im++)
#pragma unroll
        for (int in = 0; in < 4; in++)
#pragma unroll
            for (int r = 0; r < 4; r++) acc[im][in][r] = 0.f;
    float local = 0.f;

    stage(0, 0);
    stage(1, 1);

    for (int step = 0; step < NSTEP; step++) {
        if (step == NSTEP - 1)
            asm volatile("cp.async.wait_group 0;" ::: "memory");
        else
            asm volatile("cp.async.wait_group 1;" ::: "memory");
        __syncthreads();
        if (step < NSTEP - 2) stage(step + 2, (step + 2) % NBUF);

        int kc = step & 7;
        int buf = step % NBUF;
        uint32_t abase = sbase + XC_OFF + buf * XC_BYTES;
        uint32_t bko = sbase + (uint32_t)(kc * 64 * 2);

#pragma unroll
        for (int ks = 0; ks < 4; ks++) {
            uint32_t a[4][4], bb[2][4];
#pragma unroll
            for (int im = 0; im < 4; im++) ldsm4(a[im], abase + aRow[im] + ks * 32);
#pragma unroll
            for (int g = 0; g < 2; g++) ldsm4(bb[g], bko + bRow[g] + ks * 32);
#pragma unroll
            for (int im = 0; im < 4; im++)
#pragma unroll
                for (int in = 0; in < 4; in++)
                    asm volatile(
                        "mma.sync.aligned.m16n8k16.row.col.f32.bf16.bf16.f32 "
                        "{%0,%1,%2,%3}, {%4,%5,%6,%7}, {%8,%9}, {%0,%1,%2,%3};"
                        : "+f"(acc[im][in][0]), "+f"(acc[im][in][1]),
                          "+f"(acc[im][in][2]), "+f"(acc[im][in][3])
                        : "r"(a[im][0]), "r"(a[im][1]), "r"(a[im][2]), "r"(a[im][3]),
                          "r"(bb[in >> 1][(in & 1) * 2]), "r"(bb[in >> 1][(in & 1) * 2 + 1]));
        }

        // ---- m-block epilogue (registers -> scalar) ----
        if (kc == 7) {
            int mb = step >> 3;
            int rbase = mb * 128 + warp_m * 64 + (lane >> 2);
#pragma unroll
            for (int im = 0; im < 4; im++) {
                float b0 = MARGIN - g_t[rbase + im * 16];
                float b1 = MARGIN - g_t[rbase + im * 16 + 8];
#pragma unroll
                for (int in = 0; in < 4; in++) {
                    int c = warp_n * 32 + in * 8 + (lane & 3) * 2;
                    float i0 = invn[c], i1 = invn[c + 1];
                    float v0 = vmsk[c], v1 = vmsk[c + 1];
                    local += v0 * fmaxf(0.f, fmaf(acc[im][in][0], i0, b0));
                    local += v1 * fmaxf(0.f, fmaf(acc[im][in][1], i1, b0));
                    local += v0 * fmaxf(0.f, fmaf(acc[im][in][2], i0, b1));
                    local += v1 * fmaxf(0.f, fmaf(acc[im][in][3], i1, b1));
                    acc[im][in][0] = 0.f; acc[im][in][1] = 0.f;
                    acc[im][in][2] = 0.f; acc[im][in][3] = 0.f;
                }
            }
        }
    }

    // ---- CTA reduction to one scalar ----
#pragma unroll
    for (int off = 16; off > 0; off >>= 1)
        local += __shfl_xor_sync(0xffffffffu, local, off);
    __shared__ float red[8];
    if (lane == 0) red[wid] = local;
    __syncthreads();
    if (tid == 0) {
        float s = 0.f;
#pragma unroll
        for (int w = 0; w < 8; w++) s += red[w];
        g_partial[blockIdx.x] = s;
    }
}

// ---------------------------------------------------------------------------
// Kernel 4: reduce 782 per-CTA scalars
// ---------------------------------------------------------------------------
__global__ void k_final(float* __restrict__ out) {
    int tid = threadIdx.x; // 1024
    float s = (tid < NTILES) ? g_partial[tid] : 0.f;
#pragma unroll
    for (int off = 16; off > 0; off >>= 1) s += __shfl_xor_sync(0xffffffffu, s, off);
    __shared__ float sm[32];
    int lane = tid & 31, wid = tid >> 5;
    if (lane == 0) sm[wid] = s;
    __syncthreads();
    if (tid < 32) {
        float v = sm[tid];
#pragma unroll
        for (int off = 16; off > 0; off >>= 1) v += __shfl_xor_sync(0xffffffffu, v, off);
        if (tid == 0) out[0] = v / (float)B_N - MARGIN;
    }
}

// ---------------------------------------------------------------------------
extern "C" void kernel_launch(void* const* d_in, const int* in_sizes, int n_in,
                              void* d_out, int out_size) {
    const float* X = (const float*)d_in[0];   // [1024, 512] fp32
    const float* E = (const float*)d_in[1];   // [100000, 512] fp32
    const int* T = (const int*)d_in[2];       // [1024] int32
    float* out = (float*)d_out;

    cudaFuncSetAttribute(k_main, cudaFuncAttributeMaxDynamicSharedMemorySize,
                         SMEM_BYTES);

    k_norm<<<B_N, 128>>>(X);
    k_target<<<B_N, 128>>>(X, E, T);
    k_main<<<NTILES, 256, SMEM_BYTES>>>(E);
    k_final<<<1, 1024>>>(out);
}

// round 6
// speedup vs baseline: 1.4414x; 1.1209x over previous
#include <cuda_runtime.h>
#include <cuda_bf16.h>
#include <cstdint>

#define B_N 1024
#define D_N 512
#define C_N 100000
#define MARGIN 0.1f
#define EPSV 1e-8f
#define XSCL 16.0f                   // fp8 pre-scale for normalized X

#define NT 128                       // classes per CTA tile
#define NTILES 782
#define NMB 8                        // 1024/128 row blocks
#define NKC 8                        // 512/64 k-chunks per m-block
#define NSTEP (NMB * NKC)
#define ES_STRB 528                  // E smem row stride bytes (512 fp8 + 16 pad)
#define XR_BYTES 80                  // X chunk row stride bytes (64 fp8 + 16 pad)

#define XC_OFF (NT * ES_STRB)        // 67584
#define XC_BYTES (128 * XR_BYTES)    // 10240
#define NBUF 3
#define INVN_OFF (XC_OFF + NBUF * XC_BYTES)  // 98304
#define VM_OFF (INVN_OFF + 512)
#define SMEM_BYTES (VM_OFF + 512)            // 99328 -> 2 CTAs/SM

__device__ __align__(128) unsigned char g_Xq[B_N * D_N]; // fp8 e4m3, x_n * 16
__device__ float g_t[B_N];
__device__ float g_partial[NTILES];

// ---------------------------------------------------------------------------
__device__ __forceinline__ uint32_t smem_u32(const void* p) {
    uint32_t a;
    asm("{ .reg .u64 t; cvta.to.shared.u64 t, %1; cvt.u32.u64 %0, t; }" : "=r"(a) : "l"(p));
    return a;
}
__device__ __forceinline__ void cp16(uint32_t dst, const void* src) {
    asm volatile("cp.async.cg.shared.global [%0], [%1], 16;" :: "r"(dst), "l"(src));
}
__device__ __forceinline__ void ldsm4(uint32_t* r, uint32_t a) {
    asm volatile("ldmatrix.sync.aligned.m8n8.x4.shared.b16 {%0,%1,%2,%3}, [%4];"
                 : "=r"(r[0]), "=r"(r[1]), "=r"(r[2]), "=r"(r[3]) : "r"(a));
}
// pack 4 floats -> 4 e4m3 bytes (x lowest byte)
__device__ __forceinline__ uint32_t f4_to_e4m3x4(float x, float y, float z, float w) {
    uint32_t pk;
    asm("{ .reg .b16 lo, hi;\n"
        "cvt.rn.satfinite.e4m3x2.f32 lo, %2, %1;\n"
        "cvt.rn.satfinite.e4m3x2.f32 hi, %4, %3;\n"
        "mov.b32 %0, {lo, hi}; }"
        : "=r"(pk) : "f"(x), "f"(y), "f"(z), "f"(w));
    return pk;
}

// ---------------------------------------------------------------------------
// Kernel 1: row-normalize X -> fp8 (scaled by 16)
// ---------------------------------------------------------------------------
__global__ void k_norm(const float* __restrict__ X) {
    int b = blockIdx.x;
    int t = threadIdx.x; // 128 threads, 4 floats each
    float4 v = *(const float4*)(X + (size_t)b * D_N + 4 * t);
    float ss = v.x * v.x + v.y * v.y + v.z * v.z + v.w * v.w;
    __shared__ float sm[128];
    sm[t] = ss;
    __syncthreads();
    for (int s = 64; s > 0; s >>= 1) {
        if (t < s) sm[t] += sm[t + s];
        __syncthreads();
    }
    float inv = XSCL / fmaxf(sqrtf(sm[0]), EPSV);
    *(uint32_t*)(g_Xq + (size_t)b * D_N + 4 * t) =
        f4_to_e4m3x4(v.x * inv, v.y * inv, v.z * inv, v.w * inv);
}

// ---------------------------------------------------------------------------
// Kernel 2: fp32-exact target cosine (targets int32)
// ---------------------------------------------------------------------------
__global__ void k_target(const float* __restrict__ X, const float* __restrict__ E,
                         const int* __restrict__ T) {
    int b = blockIdx.x;
    int tid = threadIdx.x;
    int tg = max(0, min(T[b], C_N - 1));
    const float* x = X + (size_t)b * D_N;
    const float* e = E + (size_t)tg * D_N;
    float sxx = 0.f, see = 0.f, sxe = 0.f;
#pragma unroll
    for (int j = 0; j < 4; j++) {
        float xv = x[tid + j * 128];
        float ev = e[tid + j * 128];
        sxx += xv * xv; see += ev * ev; sxe += xv * ev;
    }
    __shared__ float s1[128], s2[128], s3[128];
    s1[tid] = sxx; s2[tid] = see; s3[tid] = sxe;
    __syncthreads();
    for (int s = 64; s > 0; s >>= 1) {
        if (tid < s) { s1[tid] += s1[tid + s]; s2[tid] += s2[tid + s]; s3[tid] += s3[tid + s]; }
        __syncthreads();
    }
    if (tid == 0)
        g_t[b] = s3[0] / (fmaxf(sqrtf(s1[0]), EPSV) * fmaxf(sqrtf(s2[0]), EPSV));
}

// ---------------------------------------------------------------------------
// Kernel 3: fp8 m16n8k32 mma.sync GEMM + fused hinge -> scalar per CTA
// ---------------------------------------------------------------------------
__global__ __launch_bounds__(256, 2) void k_main(const float* __restrict__ E) {
    extern __shared__ __align__(1024) unsigned char smem[];
    uint32_t sbase = smem_u32(smem);
    float* invn = (float*)(smem + INVN_OFF);
    float* vmsk = (float*)(smem + VM_OFF);
    int tid = threadIdx.x, lane = tid & 31, wid = tid >> 5;
    int warp_m = wid >> 2;  // 0..1 -> 64 rows
    int warp_n = wid & 3;   // 0..3 -> 32 classes
    int c0 = blockIdx.x * NT;

    // ---- Phase 1: E tile fp32->e4m3 + inv-norms (/16 folded) + validity ----
    {
        int cl = tid >> 1, pr = tid & 1;
        int gc = c0 + cl;
        bool vld = gc < C_N;
        const float4* src = (const float4*)(E + (size_t)(vld ? gc : 0) * D_N);
        float ss = 0.f;
#pragma unroll 8
        for (int i = 0; i < 64; i++) {
            int f4 = pr + 2 * i;
            float4 v = vld ? src[f4] : make_float4(0.f, 0.f, 0.f, 0.f);
            ss += v.x * v.x + v.y * v.y + v.z * v.z + v.w * v.w;
            *(uint32_t*)(smem + cl * ES_STRB + f4 * 4) =
                f4_to_e4m3x4(v.x, v.y, v.z, v.w);
        }
        ss += __shfl_xor_sync(0xffffffffu, ss, 1);
        if (pr == 0) {
            invn[cl] = vld ? (1.0f / (fmaxf(sqrtf(ss), EPSV) * XSCL)) : 0.f;
            vmsk[cl] = vld ? 1.f : 0.f;
        }
    }
    __syncthreads();

    // ---- fragment addresses (relative, bytes) ----
    uint32_t aRow[4];
#pragma unroll
    for (int im = 0; im < 4; im++)
        aRow[im] = (uint32_t)((warp_m * 64 + im * 16 + (lane & 15)) * XR_BYTES +
                              (lane >> 4) * 16);
    uint32_t bRow[2];
#pragma unroll
    for (int g = 0; g < 2; g++)
        bRow[g] = (uint32_t)((warp_n * 32 + g * 16 + (lane & 15)) * ES_STRB +
                             (lane >> 4) * 16);

    auto stage = [&](int s, int buf) {
        int mb = s >> 3, kc = s & 7;
        const char* src = (const char*)g_Xq + (size_t)mb * 128 * 512 + kc * 64;
        uint32_t dst = sbase + XC_OFF + buf * XC_BYTES;
#pragma unroll
        for (int j = 0; j < 2; j++) {
            int i = tid + j * 256;
            int row = i >> 2, seg = i & 3;
            cp16(dst + row * XR_BYTES + seg * 16, src + (size_t)row * 512 + seg * 16);
        }
        asm volatile("cp.async.commit_group;" ::: "memory");
    };

    float acc[4][4][4];
#pragma unroll
    for (int im = 0; im < 4; im++)
#pragma unroll
        for (int in = 0; in < 4; in++)
#pragma unroll
            for (int r = 0; r < 4; r++) acc[im][in][r] = 0.f;
    float local = 0.f;

    stage(0, 0);
    stage(1, 1);

    for (int step = 0; step < NSTEP; step++) {
        if (step == NSTEP - 1)
            asm volatile("cp.async.wait_group 0;" ::: "memory");
        else
            asm volatile("cp.async.wait_group 1;" ::: "memory");
        __syncthreads();
        if (step < NSTEP - 2) stage(step + 2, (step + 2) % NBUF);

        int kc = step & 7;
        int buf = step % NBUF;
        uint32_t abase = sbase + XC_OFF + buf * XC_BYTES;
        uint32_t bko = sbase + (uint32_t)(kc * 64);

#pragma unroll
        for (int ks = 0; ks < 2; ks++) {  // two k32 steps per 64-k chunk
            uint32_t a[4][4], bb[2][4];
#pragma unroll
            for (int im = 0; im < 4; im++) ldsm4(a[im], abase + aRow[im] + ks * 32);
#pragma unroll
            for (int g = 0; g < 2; g++) ldsm4(bb[g], bko + bRow[g] + ks * 32);
#pragma unroll
            for (int im = 0; im < 4; im++)
#pragma unroll
                for (int in = 0; in < 4; in++)
                    asm volatile(
                        "mma.sync.aligned.m16n8k32.row.col.f32.e4m3.e4m3.f32 "
                        "{%0,%1,%2,%3}, {%4,%5,%6,%7}, {%8,%9}, {%0,%1,%2,%3};"
                        : "+f"(acc[im][in][0]), "+f"(acc[im][in][1]),
                          "+f"(acc[im][in][2]), "+f"(acc[im][in][3])
                        : "r"(a[im][0]), "r"(a[im][1]), "r"(a[im][2]), "r"(a[im][3]),
                          "r"(bb[in >> 1][in & 1]), "r"(bb[in >> 1][(in & 1) + 2]));
        }

        // ---- m-block epilogue ----
        if (kc == 7) {
            int mb = step >> 3;
            int rbase = mb * 128 + warp_m * 64 + (lane >> 2);
#pragma unroll
            for (int im = 0; im < 4; im++) {
                float b0 = MARGIN - g_t[rbase + im * 16];
                float b1 = MARGIN - g_t[rbase + im * 16 + 8];
#pragma unroll
                for (int in = 0; in < 4; in++) {
                    int c = warp_n * 32 + in * 8 + (lane & 3) * 2;
                    float i0 = invn[c], i1 = invn[c + 1];
                    float v0 = vmsk[c], v1 = vmsk[c + 1];
                    local += v0 * fmaxf(0.f, fmaf(acc[im][in][0], i0, b0));
                    local += v1 * fmaxf(0.f, fmaf(acc[im][in][1], i1, b0));
                    local += v0 * fmaxf(0.f, fmaf(acc[im][in][2], i0, b1));
                    local += v1 * fmaxf(0.f, fmaf(acc[im][in][3], i1, b1));
                    acc[im][in][0] = 0.f; acc[im][in][1] = 0.f;
                    acc[im][in][2] = 0.f; acc[im][in][3] = 0.f;
                }
            }
        }
    }

    // ---- CTA reduction ----
#pragma unroll
    for (int off = 16; off > 0; off >>= 1)
        local += __shfl_xor_sync(0xffffffffu, local, off);
    __shared__ float red[8];
    if (lane == 0) red[wid] = local;
    __syncthreads();
    if (tid == 0) {
        float s = 0.f;
#pragma unroll
        for (int w = 0; w < 8; w++) s += red[w];
        g_partial[blockIdx.x] = s;
    }
}

// ---------------------------------------------------------------------------
// Kernel 4: reduce 782 per-CTA scalars
// ---------------------------------------------------------------------------
__global__ void k_final(float* __restrict__ out) {
    int tid = threadIdx.x; // 1024
    float s = (tid < NTILES) ? g_partial[tid] : 0.f;
#pragma unroll
    for (int off = 16; off > 0; off >>= 1) s += __shfl_xor_sync(0xffffffffu, s, off);
    __shared__ float sm[32];
    int lane = tid & 31, wid = tid >> 5;
    if (lane == 0) sm[wid] = s;
    __syncthreads();
    if (tid < 32) {
        float v = sm[tid];
#pragma unroll
        for (int off = 16; off > 0; off >>= 1) v += __shfl_xor_sync(0xffffffffu, v, off);
        if (tid == 0) out[0] = v / (float)B_N - MARGIN;
    }
}

// ---------------------------------------------------------------------------
extern "C" void kernel_launch(void* const* d_in, const int* in_sizes, int n_in,
                              void* d_out, int out_size) {
    const float* X = (const float*)d_in[0];   // [1024, 512] fp32
    const float* E = (const float*)d_in[1];   // [100000, 512] fp32
    const int* T = (const int*)d_in[2];       // [1024] int32
    float* out = (float*)d_out;

    cudaFuncSetAttribute(k_main, cudaFuncAttributeMaxDynamicSharedMemorySize,
                         SMEM_BYTES);

    k_norm<<<B_N, 128>>>(X);
    k_target<<<B_N, 128>>>(X, E, T);
    k_main<<<NTILES, 256, SMEM_BYTES>>>(E);
    k_final<<<1, 1024>>>(out);
}